// round 1
// baseline (speedup 1.0000x reference)
#include <cuda_runtime.h>
#include <cstdint>

// ---- model constants ----
constexpr int Bb = 32, Tt = 128, Dd = 128, Hh = 8, HDh = 16, Ll = 4;
constexpr int Vv = 50257;
constexpr int BT = Bb * Tt;           // 4096
constexpr int VP = 50304;             // V padded to multiple of 128

// ---- scratch (static device globals; no allocation allowed) ----
__device__ float g_x  [BT * Dd];
__device__ float g_h  [BT * Dd];
__device__ float g_qkv[BT * 3 * Dd];
__device__ float g_att[BT * Dd];
__device__ float g_mlp[BT * 4 * Dd];
__device__ float g_wqkv[Ll * Dd * 3 * Dd];
__device__ float g_lmw [Dd * VP];
__device__ float g_rowsum[BT];

__device__ __forceinline__ float* buf_sel(int s) {
    switch (s) {
        case 0: return g_x;
        case 1: return g_h;
        case 2: return g_qkv;
        case 3: return g_att;
        default: return g_mlp;
    }
}

// ---- prep: pack wq/wk/wv into [L][D][384] (q|k|v cols), zero rowsum ----
__global__ void prep_kernel(const float* __restrict__ wq,
                            const float* __restrict__ wk,
                            const float* __restrict__ wv) {
    int i = blockIdx.x * blockDim.x + threadIdx.x;   // over L*H*D*HD = 65536
    if (i < BT) g_rowsum[i] = 0.f;
    if (i < Ll * Hh * Dd * HDh) {
        int e = i & 15;
        int d = (i >> 4) & 127;
        int h = (i >> 11) & 7;
        int l = i >> 14;
        int dst = (l * Dd + d) * 384 + h * HDh + e;
        g_wqkv[dst]       = wq[i];
        g_wqkv[dst + 128] = wk[i];
        g_wqkv[dst + 256] = wv[i];
    }
}

// ---- pad lm_w [D,V] -> [D,VP] zero-padded ----
__global__ void padlmw_kernel(const float* __restrict__ lm_w) {
    int i = blockIdx.x * blockDim.x + threadIdx.x;
    if (i >= Dd * VP) return;
    int d = i / VP, c = i - d * VP;
    g_lmw[i] = (c < Vv) ? lm_w[(size_t)d * Vv + c] : 0.f;
}

// ---- embedding ----
__global__ void embed_kernel(const int* __restrict__ idx,
                             const float* __restrict__ tok,
                             const float* __restrict__ pos) {
    int bt = blockIdx.x, d = threadIdx.x;
    int t = bt & (Tt - 1);
    g_x[bt * Dd + d] = tok[(size_t)idx[bt] * Dd + d] + pos[t * Dd + d];
}

// ---- layernorm: g_x -> g_h ----
__global__ void ln_kernel(const float* __restrict__ g, const float* __restrict__ b) {
    int row = blockIdx.x, tid = threadIdx.x;
    float v = g_x[row * Dd + tid];
    float s = v, s2 = v * v;
    #pragma unroll
    for (int o = 16; o; o >>= 1) {
        s  += __shfl_xor_sync(0xffffffffu, s,  o);
        s2 += __shfl_xor_sync(0xffffffffu, s2, o);
    }
    __shared__ float sh[8];
    int w = tid >> 5;
    if ((tid & 31) == 0) { sh[w] = s; sh[4 + w] = s2; }
    __syncthreads();
    float ts  = sh[0] + sh[1] + sh[2] + sh[3];
    float ts2 = sh[4] + sh[5] + sh[6] + sh[7];
    float mean = ts * (1.f / 128.f);
    float var  = ts2 * (1.f / 128.f) - mean * mean;
    g_h[row * Dd + tid] = (v - mean) * rsqrtf(var + 1e-5f) * g[tid] + b[tid];
}

// ---- generic body GEMM: C = A@B (+bias)(relu)(+res g_x), 64x64 tile, BK=32 ----
__global__ __launch_bounds__(256)
void gemm64_kernel(int asel, const float* __restrict__ Bext, int bofs,
                   const float* __restrict__ bias, int use_res, int csel,
                   int N, int K, int relu) {
    __shared__ float As[32][65];
    __shared__ __align__(16) float Bs[32][64];
    const float* A = buf_sel(asel);
    float* C = buf_sel(csel);
    const float* Bm = Bext ? Bext : (g_wqkv + bofs);
    int tid = threadIdx.x;
    int tx = tid & 15, ty = tid >> 4;
    int r0 = blockIdx.y * 64, c0 = blockIdx.x * 64;
    int ar = tid >> 3, ak = (tid & 7) * 4;
    int br = tid >> 4, bc = (tid & 15) * 4;
    float acc[4][4] = {};
    for (int k0 = 0; k0 < K; k0 += 32) {
        float4 a0 = *(const float4*)&A[(size_t)(r0 + ar)      * K + k0 + ak];
        float4 a1 = *(const float4*)&A[(size_t)(r0 + ar + 32) * K + k0 + ak];
        As[ak + 0][ar] = a0.x; As[ak + 1][ar] = a0.y;
        As[ak + 2][ar] = a0.z; As[ak + 3][ar] = a0.w;
        As[ak + 0][ar + 32] = a1.x; As[ak + 1][ar + 32] = a1.y;
        As[ak + 2][ar + 32] = a1.z; As[ak + 3][ar + 32] = a1.w;
        *(float4*)&Bs[br][bc]      = *(const float4*)&Bm[(size_t)(k0 + br)      * N + c0 + bc];
        *(float4*)&Bs[br + 16][bc] = *(const float4*)&Bm[(size_t)(k0 + br + 16) * N + c0 + bc];
        __syncthreads();
        #pragma unroll
        for (int kk = 0; kk < 32; kk++) {
            float4 bv = *(const float4*)&Bs[kk][tx * 4];
            float a0r = As[kk][ty * 4 + 0];
            float a1r = As[kk][ty * 4 + 1];
            float a2r = As[kk][ty * 4 + 2];
            float a3r = As[kk][ty * 4 + 3];
            acc[0][0] += a0r * bv.x; acc[0][1] += a0r * bv.y; acc[0][2] += a0r * bv.z; acc[0][3] += a0r * bv.w;
            acc[1][0] += a1r * bv.x; acc[1][1] += a1r * bv.y; acc[1][2] += a1r * bv.z; acc[1][3] += a1r * bv.w;
            acc[2][0] += a2r * bv.x; acc[2][1] += a2r * bv.y; acc[2][2] += a2r * bv.z; acc[2][3] += a2r * bv.w;
            acc[3][0] += a3r * bv.x; acc[3][1] += a3r * bv.y; acc[3][2] += a3r * bv.z; acc[3][3] += a3r * bv.w;
        }
        __syncthreads();
    }
    #pragma unroll
    for (int i = 0; i < 4; i++) {
        int rr = r0 + ty * 4 + i;
        #pragma unroll
        for (int j = 0; j < 4; j++) {
            int cc = c0 + tx * 4 + j;
            float v = acc[i][j];
            if (bias) v += bias[cc];
            if (relu) v = fmaxf(v, 0.f);
            if (use_res) v += g_x[(size_t)rr * N + cc];
            C[(size_t)rr * N + cc] = v;
        }
    }
}

// ---- attention: per (b,h) block, causal softmax, scale = D^-0.5 ----
__global__ void attn_kernel() {
    __shared__ float k_s[16][129];
    __shared__ float v_s[16][129];
    __shared__ float p_s[4][128];
    int bh = blockIdx.x;
    int b = bh >> 3, h = bh & 7;
    int tid = threadIdx.x;
    int w = tid >> 5, lane = tid & 31;
    int base_bt = b * Tt;
    for (int i = tid; i < Tt * HDh; i += 128) {
        int s = i >> 4, e = i & 15;
        size_t g = (size_t)(base_bt + s) * 384 + h * HDh + e;
        k_s[e][s] = g_qkv[g + 128];
        v_s[e][s] = g_qkv[g + 256];
    }
    __syncthreads();
    const float scale = 0.08838834764831845f;  // D^-0.5
    for (int t = w; t < Tt; t += 4) {
        float q[16];
        size_t qg = (size_t)(base_bt + t) * 384 + h * HDh;
        #pragma unroll
        for (int e = 0; e < 16; e++) q[e] = g_qkv[qg + e];
        float sc[4];
        #pragma unroll
        for (int j = 0; j < 4; j++) {
            int s = lane + 32 * j;
            float dot = 0.f;
            #pragma unroll
            for (int e = 0; e < 16; e++) dot += q[e] * k_s[e][s];
            sc[j] = (s <= t) ? dot * scale : -1e30f;
        }
        float m = fmaxf(fmaxf(sc[0], sc[1]), fmaxf(sc[2], sc[3]));
        #pragma unroll
        for (int o = 16; o; o >>= 1) m = fmaxf(m, __shfl_xor_sync(0xffffffffu, m, o));
        float p[4], ps = 0.f;
        #pragma unroll
        for (int j = 0; j < 4; j++) {
            int s = lane + 32 * j;
            p[j] = (s <= t) ? __expf(sc[j] - m) : 0.f;
            ps += p[j];
        }
        #pragma unroll
        for (int o = 16; o; o >>= 1) ps += __shfl_xor_sync(0xffffffffu, ps, o);
        float inv = 1.f / ps;
        #pragma unroll
        for (int j = 0; j < 4; j++) p_s[w][lane + 32 * j] = p[j] * inv;
        __syncwarp();
        int e = lane & 15, half = lane >> 4;
        float acc = 0.f;
        int sb = half * 64;
        #pragma unroll
        for (int s = 0; s < 64; s++) acc += p_s[w][sb + s] * v_s[e][sb + s];
        acc += __shfl_xor_sync(0xffffffffu, acc, 16);
        if (lane < 16) g_att[(size_t)(base_bt + t) * Dd + h * HDh + e] = acc;
        __syncwarp();
    }
}

// ---- LM head: logits = g_h @ g_lmw (+lm_b), 128x128 tile, f32x2 packed FMA.
//      Also accumulates per-row sum(exp(logit)) into g_rowsum. ----
__global__ __launch_bounds__(256)
void lmhead_kernel(const float* __restrict__ lmb, float* __restrict__ out) {
    __shared__ float As[32][129];
    __shared__ __align__(16) float Bs[32][128];
    __shared__ float rsum[128];
    int tid = threadIdx.x;
    int tx = tid & 15, ty = tid >> 4;
    int r0 = blockIdx.y * 128, c0 = blockIdx.x * 128;
    if (tid < 128) rsum[tid] = 0.f;
    unsigned long long acc2[8][4];
    #pragma unroll
    for (int i = 0; i < 8; i++)
        #pragma unroll
        for (int j = 0; j < 4; j++) acc2[i][j] = 0ull;
    int ar = tid >> 3, ak = (tid & 7) * 4;
    int bk = tid >> 5, bc = (tid & 31) * 4;
    for (int k0 = 0; k0 < 128; k0 += 32) {
        #pragma unroll
        for (int p = 0; p < 4; p++) {
            float4 a = *(const float4*)&g_h[(size_t)(r0 + ar + 32 * p) * Dd + k0 + ak];
            As[ak + 0][ar + 32 * p] = a.x;
            As[ak + 1][ar + 32 * p] = a.y;
            As[ak + 2][ar + 32 * p] = a.z;
            As[ak + 3][ar + 32 * p] = a.w;
            *(float4*)&Bs[bk + 8 * p][bc] =
                *(const float4*)&g_lmw[(size_t)(k0 + bk + 8 * p) * VP + c0 + bc];
        }
        __syncthreads();
        #pragma unroll
        for (int kk = 0; kk < 32; kk++) {
            const unsigned long long* bp = (const unsigned long long*)&Bs[kk][tx * 8];
            unsigned long long b0 = bp[0], b1 = bp[1], b2 = bp[2], b3 = bp[3];
            #pragma unroll
            for (int i = 0; i < 8; i++) {
                unsigned au = __float_as_uint(As[kk][ty * 8 + i]);
                unsigned long long av;
                asm("mov.b64 %0, {%1, %1};" : "=l"(av) : "r"(au));
                asm("fma.rn.f32x2 %0, %1, %2, %0;" : "+l"(acc2[i][0]) : "l"(av), "l"(b0));
                asm("fma.rn.f32x2 %0, %1, %2, %0;" : "+l"(acc2[i][1]) : "l"(av), "l"(b1));
                asm("fma.rn.f32x2 %0, %1, %2, %0;" : "+l"(acc2[i][2]) : "l"(av), "l"(b2));
                asm("fma.rn.f32x2 %0, %1, %2, %0;" : "+l"(acc2[i][3]) : "l"(av), "l"(b3));
            }
        }
        __syncthreads();
    }
    float rowexp[8];
    #pragma unroll
    for (int i = 0; i < 8; i++) {
        rowexp[i] = 0.f;
        int rr = r0 + ty * 8 + i;
        size_t ro = (size_t)rr * Vv;
        #pragma unroll
        for (int j = 0; j < 4; j++) {
            int cA = c0 + tx * 8 + 2 * j;
            float vA = __uint_as_float((unsigned)(acc2[i][j] & 0xffffffffull));
            float vB = __uint_as_float((unsigned)(acc2[i][j] >> 32));
            if (cA < Vv) {
                vA += lmb[cA];
                if (out) out[ro + cA] = vA;
                rowexp[i] += __expf(vA);
            }
            if (cA + 1 < Vv) {
                vB += lmb[cA + 1];
                if (out) out[ro + cA + 1] = vB;
                rowexp[i] += __expf(vB);
            }
        }
    }
    #pragma unroll
    for (int i = 0; i < 8; i++) atomicAdd(&rsum[ty * 8 + i], rowexp[i]);
    __syncthreads();
    if (tid < 128) atomicAdd(&g_rowsum[r0 + tid], rsum[tid]);
}

// ---- loss: mean_r [ log(rowsumexp_r) - (x_r . lm_w[:,tgt] + lm_b[tgt]) ] ----
__global__ void loss_kernel(const int* __restrict__ targets,
                            const float* __restrict__ lm_w,
                            const float* __restrict__ lmb,
                            float* __restrict__ loss_out) {
    int tid = threadIdx.x;
    float local = 0.f;
    for (int r = tid; r < BT; r += 1024) {
        int tgt = targets[r];
        float dot = lmb[tgt];
        const float* xr = &g_h[(size_t)r * Dd];
        #pragma unroll 8
        for (int d = 0; d < Dd; d++) dot += xr[d] * lm_w[(size_t)d * Vv + tgt];
        local += logf(g_rowsum[r]) - dot;
    }
    #pragma unroll
    for (int o = 16; o; o >>= 1) local += __shfl_xor_sync(0xffffffffu, local, o);
    __shared__ float red[32];
    if ((tid & 31) == 0) red[tid >> 5] = local;
    __syncthreads();
    if (tid < 32) {
        float v = red[tid];
        #pragma unroll
        for (int o = 16; o; o >>= 1) v += __shfl_xor_sync(0xffffffffu, v, o);
        if (tid == 0 && loss_out) *loss_out = v * (1.f / (float)BT);
    }
}

extern "C" void kernel_launch(void* const* d_in, const int* in_sizes, int n_in,
                              void* d_out, int out_size) {
    const int*   idx     = (const int*)  d_in[0];
    const int*   targets = (const int*)  d_in[1];
    const float* tok_emb = (const float*)d_in[2];
    const float* pos_emb = (const float*)d_in[3];
    const float* wq      = (const float*)d_in[4];
    const float* wk      = (const float*)d_in[5];
    const float* wv      = (const float*)d_in[6];
    const float* wproj   = (const float*)d_in[7];
    const float* bproj   = (const float*)d_in[8];
    const float* w1      = (const float*)d_in[9];
    const float* b1      = (const float*)d_in[10];
    const float* w2      = (const float*)d_in[11];
    const float* b2      = (const float*)d_in[12];
    const float* ln1_g   = (const float*)d_in[13];
    const float* ln1_b   = (const float*)d_in[14];
    const float* ln2_g   = (const float*)d_in[15];
    const float* ln2_b   = (const float*)d_in[16];
    const float* lnf_g   = (const float*)d_in[17];
    const float* lnf_b   = (const float*)d_in[18];
    const float* lm_w    = (const float*)d_in[19];
    const float* lm_b    = (const float*)d_in[20];

    float* outf = (float*)d_out;
    long long btv = (long long)BT * Vv;
    float* logits = ((long long)out_size >= btv) ? outf : nullptr;
    float* lossp  = nullptr;
    if ((long long)out_size == btv + 1) lossp = outf + btv;
    else if ((long long)out_size < btv && out_size >= 1) lossp = outf + (out_size - 1);

    prep_kernel<<<256, 256>>>(wq, wk, wv);
    padlmw_kernel<<<(Dd * VP + 255) / 256, 256>>>(lm_w);
    embed_kernel<<<BT, 128>>>(idx, tok_emb, pos_emb);

    for (int l = 0; l < Ll; l++) {
        // h = ln1(x)
        ln_kernel<<<BT, 128>>>(ln1_g + l * Dd, ln1_b + l * Dd);
        // qkv = h @ wqkv_packed[l]   (N=384, K=128)
        gemm64_kernel<<<dim3(384 / 64, BT / 64), 256>>>(
            1, nullptr, l * Dd * 384, nullptr, 0, 2, 384, 128, 0);
        // attention -> g_att
        attn_kernel<<<Bb * Hh, 128>>>();
        // x = x + att @ wproj + bproj  (N=128, K=128)
        gemm64_kernel<<<dim3(128 / 64, BT / 64), 256>>>(
            3, wproj + (size_t)l * Dd * Dd, 0, bproj + l * Dd, 1, 0, 128, 128, 0);
        // h = ln2(x)
        ln_kernel<<<BT, 128>>>(ln2_g + l * Dd, ln2_b + l * Dd);
        // mlp = relu(h @ w1 + b1)   (N=512, K=128)
        gemm64_kernel<<<dim3(512 / 64, BT / 64), 256>>>(
            1, w1 + (size_t)l * Dd * 4 * Dd, 0, b1 + l * 4 * Dd, 0, 4, 512, 128, 1);
        // x = x + mlp @ w2 + b2     (N=128, K=512)
        gemm64_kernel<<<dim3(128 / 64, BT / 64), 256>>>(
            4, w2 + (size_t)l * 4 * Dd * Dd, 0, b2 + l * Dd, 1, 0, 128, 512, 0);
    }
    // h = ln_f(x)
    ln_kernel<<<BT, 128>>>(lnf_g, lnf_b);
    // logits + per-row sumexp
    lmhead_kernel<<<dim3(VP / 128, BT / 128), 256>>>(lm_b, logits);
    // loss
    loss_kernel<<<1, 1024>>>(targets, lm_w, lm_b, lossp);
}

// round 4
// speedup vs baseline: 1.8384x; 1.8384x over previous
#include <cuda_runtime.h>
#include <cuda_bf16.h>
#include <cstdint>

// ---- model constants ----
constexpr int Bb = 32, Tt = 128, Dd = 128, Hh = 8, HDh = 16, Ll = 4;
constexpr int Vv = 50257;
constexpr int BT = Bb * Tt;           // 4096
constexpr int VP = 50304;             // V padded to multiple of 128

// ---- scratch (static device globals; no allocation allowed) ----
__device__ float g_x  [BT * Dd];
__device__ float g_h  [BT * Dd];
__device__ float g_qkv[BT * 3 * Dd];
__device__ float g_att[BT * Dd];      // reused as per-row nll scratch at the end
__device__ float g_mlp[BT * 4 * Dd];
__device__ float g_wqkv[Ll * Dd * 3 * Dd];
__device__ float g_rowsum[BT];
__device__ __align__(16) __nv_bfloat16 g_lmwb[(size_t)VP * 256];  // [n][0:128]=hi,[128:256]=lo
__device__ __align__(16) __nv_bfloat16 g_hb[(size_t)BT * 256];    // [r][0:128]=hi,[128:256]=lo

__device__ __forceinline__ float* buf_sel(int s) {
    switch (s) {
        case 0: return g_x;
        case 1: return g_h;
        case 2: return g_qkv;
        case 3: return g_att;
        default: return g_mlp;
    }
}

__device__ __forceinline__ uint32_t smem_u32(const void* p) {
    uint32_t a;
    asm("{ .reg .u64 t; cvta.to.shared.u64 t, %1; cvt.u32.u64 %0, t; }" : "=r"(a) : "l"(p));
    return a;
}

// ======================= small prep kernels =======================
__global__ void prep_kernel(const float* __restrict__ wq,
                            const float* __restrict__ wk,
                            const float* __restrict__ wv) {
    int i = blockIdx.x * blockDim.x + threadIdx.x;
    if (i < BT) g_rowsum[i] = 0.f;
    if (i < Ll * Hh * Dd * HDh) {
        int e = i & 15;
        int d = (i >> 4) & 127;
        int h = (i >> 11) & 7;
        int l = i >> 14;
        int dst = (l * Dd + d) * 384 + h * HDh + e;
        g_wqkv[dst]       = wq[i];
        g_wqkv[dst + 128] = wk[i];
        g_wqkv[dst + 256] = wv[i];
    }
}

// lm_w [128][Vv] -> g_lmwb [VP][256] bf16 hi|lo (transposed, zero-padded)
__global__ void convw_kernel(const float* __restrict__ lm_w) {
    __shared__ float t[32][33];
    int nb = blockIdx.x * 32, kb = blockIdx.y * 32;
    int tx = threadIdx.x, ty = threadIdx.y;
    #pragma unroll
    for (int i = 0; i < 4; i++) {
        int k = kb + ty + 8 * i, n = nb + tx;
        t[ty + 8 * i][tx] = (n < Vv) ? lm_w[(size_t)k * Vv + n] : 0.f;
    }
    __syncthreads();
    #pragma unroll
    for (int i = 0; i < 4; i++) {
        int n = nb + ty + 8 * i, k = kb + tx;
        float v = t[tx][ty + 8 * i];
        __nv_bfloat16 hi = __float2bfloat16(v);
        __nv_bfloat16 lo = __float2bfloat16(v - __bfloat162float(hi));
        size_t base = (size_t)n * 256;
        g_lmwb[base + k]       = hi;
        g_lmwb[base + 128 + k] = lo;
    }
}

// g_h [BT][128] -> g_hb [BT][256] bf16 hi|lo
__global__ void convh_kernel() {
    int i = blockIdx.x * 256 + threadIdx.x;
    if (i >= BT * Dd) return;
    int r = i >> 7, k = i & 127;
    float v = g_h[i];
    __nv_bfloat16 hi = __float2bfloat16(v);
    __nv_bfloat16 lo = __float2bfloat16(v - __bfloat162float(hi));
    g_hb[(size_t)r * 256 + k]       = hi;
    g_hb[(size_t)r * 256 + 128 + k] = lo;
}

__global__ void embed_kernel(const int* __restrict__ idx,
                             const float* __restrict__ tok,
                             const float* __restrict__ pos) {
    int bt = blockIdx.x, d = threadIdx.x;
    int t = bt & (Tt - 1);
    g_x[bt * Dd + d] = tok[(size_t)idx[bt] * Dd + d] + pos[t * Dd + d];
}

__global__ void ln_kernel(const float* __restrict__ g, const float* __restrict__ b) {
    int row = blockIdx.x, tid = threadIdx.x;
    float v = g_x[row * Dd + tid];
    float s = v, s2 = v * v;
    #pragma unroll
    for (int o = 16; o; o >>= 1) {
        s  += __shfl_xor_sync(0xffffffffu, s,  o);
        s2 += __shfl_xor_sync(0xffffffffu, s2, o);
    }
    __shared__ float sh[8];
    int w = tid >> 5;
    if ((tid & 31) == 0) { sh[w] = s; sh[4 + w] = s2; }
    __syncthreads();
    float ts  = sh[0] + sh[1] + sh[2] + sh[3];
    float ts2 = sh[4] + sh[5] + sh[6] + sh[7];
    float mean = ts * (1.f / 128.f);
    float var  = ts2 * (1.f / 128.f) - mean * mean;
    g_h[row * Dd + tid] = (v - mean) * rsqrtf(var + 1e-5f) * g[tid] + b[tid];
}

// ======================= body GEMM =======================
__global__ __launch_bounds__(256)
void gemm64_kernel(int asel, const float* __restrict__ Bext, int bofs,
                   const float* __restrict__ bias, int use_res, int csel,
                   int N, int K, int relu) {
    __shared__ float As[32][65];
    __shared__ __align__(16) float Bs[32][64];
    const float* A = buf_sel(asel);
    float* C = buf_sel(csel);
    const float* Bm = Bext ? Bext : (g_wqkv + bofs);
    int tid = threadIdx.x;
    int tx = tid & 15, ty = tid >> 4;
    int r0 = blockIdx.y * 64, c0 = blockIdx.x * 64;
    int ar = tid >> 3, ak = (tid & 7) * 4;
    int br = tid >> 4, bc = (tid & 15) * 4;
    float acc[4][4] = {};
    for (int k0 = 0; k0 < K; k0 += 32) {
        float4 a0 = *(const float4*)&A[(size_t)(r0 + ar)      * K + k0 + ak];
        float4 a1 = *(const float4*)&A[(size_t)(r0 + ar + 32) * K + k0 + ak];
        As[ak + 0][ar] = a0.x; As[ak + 1][ar] = a0.y;
        As[ak + 2][ar] = a0.z; As[ak + 3][ar] = a0.w;
        As[ak + 0][ar + 32] = a1.x; As[ak + 1][ar + 32] = a1.y;
        As[ak + 2][ar + 32] = a1.z; As[ak + 3][ar + 32] = a1.w;
        *(float4*)&Bs[br][bc]      = *(const float4*)&Bm[(size_t)(k0 + br)      * N + c0 + bc];
        *(float4*)&Bs[br + 16][bc] = *(const float4*)&Bm[(size_t)(k0 + br + 16) * N + c0 + bc];
        __syncthreads();
        #pragma unroll
        for (int kk = 0; kk < 32; kk++) {
            float4 bv = *(const float4*)&Bs[kk][tx * 4];
            float a0r = As[kk][ty * 4 + 0];
            float a1r = As[kk][ty * 4 + 1];
            float a2r = As[kk][ty * 4 + 2];
            float a3r = As[kk][ty * 4 + 3];
            acc[0][0] += a0r * bv.x; acc[0][1] += a0r * bv.y; acc[0][2] += a0r * bv.z; acc[0][3] += a0r * bv.w;
            acc[1][0] += a1r * bv.x; acc[1][1] += a1r * bv.y; acc[1][2] += a1r * bv.z; acc[1][3] += a1r * bv.w;
            acc[2][0] += a2r * bv.x; acc[2][1] += a2r * bv.y; acc[2][2] += a2r * bv.z; acc[2][3] += a2r * bv.w;
            acc[3][0] += a3r * bv.x; acc[3][1] += a3r * bv.y; acc[3][2] += a3r * bv.z; acc[3][3] += a3r * bv.w;
        }
        __syncthreads();
    }
    #pragma unroll
    for (int i = 0; i < 4; i++) {
        int rr = r0 + ty * 4 + i;
        #pragma unroll
        for (int j = 0; j < 4; j++) {
            int cc = c0 + tx * 4 + j;
            float v = acc[i][j];
            if (bias) v += bias[cc];
            if (relu) v = fmaxf(v, 0.f);
            if (use_res) v += g_x[(size_t)rr * N + cc];
            C[(size_t)rr * N + cc] = v;
        }
    }
}

// ======================= attention =======================
__global__ void attn_kernel() {
    __shared__ float k_s[16][129];
    __shared__ float v_s[16][129];
    __shared__ float p_s[4][128];
    int bh = blockIdx.x;
    int b = bh >> 3, h = bh & 7;
    int tid = threadIdx.x;
    int w = tid >> 5, lane = tid & 31;
    int base_bt = b * Tt;
    for (int i = tid; i < Tt * HDh; i += 128) {
        int s = i >> 4, e = i & 15;
        size_t g = (size_t)(base_bt + s) * 384 + h * HDh + e;
        k_s[e][s] = g_qkv[g + 128];
        v_s[e][s] = g_qkv[g + 256];
    }
    __syncthreads();
    const float scale = 0.08838834764831845f;
    for (int t = w; t < Tt; t += 4) {
        float q[16];
        size_t qg = (size_t)(base_bt + t) * 384 + h * HDh;
        #pragma unroll
        for (int e = 0; e < 16; e++) q[e] = g_qkv[qg + e];
        float sc[4];
        #pragma unroll
        for (int j = 0; j < 4; j++) {
            int s = lane + 32 * j;
            float dot = 0.f;
            #pragma unroll
            for (int e = 0; e < 16; e++) dot += q[e] * k_s[e][s];
            sc[j] = (s <= t) ? dot * scale : -1e30f;
        }
        float m = fmaxf(fmaxf(sc[0], sc[1]), fmaxf(sc[2], sc[3]));
        #pragma unroll
        for (int o = 16; o; o >>= 1) m = fmaxf(m, __shfl_xor_sync(0xffffffffu, m, o));
        float p[4], ps = 0.f;
        #pragma unroll
        for (int j = 0; j < 4; j++) {
            int s = lane + 32 * j;
            p[j] = (s <= t) ? __expf(sc[j] - m) : 0.f;
            ps += p[j];
        }
        #pragma unroll
        for (int o = 16; o; o >>= 1) ps += __shfl_xor_sync(0xffffffffu, ps, o);
        float inv = 1.f / ps;
        #pragma unroll
        for (int j = 0; j < 4; j++) p_s[w][lane + 32 * j] = p[j] * inv;
        __syncwarp();
        int e = lane & 15, half = lane >> 4;
        float acc = 0.f;
        int sb = half * 64;
        #pragma unroll
        for (int s = 0; s < 64; s++) acc += p_s[w][sb + s] * v_s[e][sb + s];
        acc += __shfl_xor_sync(0xffffffffu, acc, 16);
        if (lane < 16) g_att[(size_t)(base_bt + t) * Dd + h * HDh + e] = acc;
        __syncwarp();
    }
}

// ======================= LM head (HMMA mma.sync bf16, hi/lo split) =======================
// Block tile: 128(M) x 64(N). 8 warps = 4(m) x 2(n), warp tile 32x32.
// Smem: As 128x264 bf16 (hi|lo in k=0..255), Bs 64x264 bf16. 101376 B -> 2 blocks/SM.
constexpr int LMS = 264;  // row stride in bf16 elems (528B: 16B-aligned, 4-bank row skew)

__global__ __launch_bounds__(256, 2)
void lmhead_hmma(const float* __restrict__ lmb, float* __restrict__ out) {
    extern __shared__ __nv_bfloat16 sm[];
    __nv_bfloat16* As = sm;               // 128 x LMS
    __nv_bfloat16* Bs = sm + 128 * LMS;   // 64 x LMS
    int tid = threadIdx.x;
    int m0 = blockIdx.x * 128, n0 = blockIdx.y * 64;

    // fill A (128 rows x 256 b16) and B (64 rows x 256 b16)
    #pragma unroll
    for (int i = 0; i < 16; i++) {
        int idx = tid + i * 256;
        int r = idx >> 5, u = idx & 31;
        uint4 v = *(const uint4*)&g_hb[((size_t)(m0 + r)) * 256 + u * 8];
        *(uint4*)&As[r * LMS + u * 8] = v;
    }
    #pragma unroll
    for (int i = 0; i < 8; i++) {
        int idx = tid + i * 256;
        int r = idx >> 5, u = idx & 31;
        uint4 v = *(const uint4*)&g_lmwb[((size_t)(n0 + r)) * 256 + u * 8];
        *(uint4*)&Bs[r * LMS + u * 8] = v;
    }
    __syncthreads();

    int wid = tid >> 5, lane = tid & 31;
    int wm = (wid & 3) * 32;     // warp m offset within block tile
    int wn = (wid >> 2) * 32;    // warp n offset

    // ldmatrix base addresses (byte smem addresses)
    uint32_t a_base[2], b_base[4];
    #pragma unroll
    for (int i = 0; i < 2; i++) {
        int row = wm + i * 16 + (lane & 15);
        int col = (lane >> 4) * 8;
        a_base[i] = smem_u32(&As[row * LMS + col]);
    }
    #pragma unroll
    for (int j = 0; j < 4; j++) {
        int row = wn + j * 8 + (lane & 7);
        int col = ((lane >> 3) & 1) * 8;
        b_base[j] = smem_u32(&Bs[row * LMS + col]);
    }

    float acc[2][4][4];
    #pragma unroll
    for (int i = 0; i < 2; i++)
        #pragma unroll
        for (int j = 0; j < 4; j++)
            #pragma unroll
            for (int q = 0; q < 4; q++) acc[i][j][q] = 0.f;

    // 3 products: (Ah,Bh) (Al,Bh) (Ah,Bl); k-offsets in BYTES (128 elems = 256B)
    #pragma unroll
    for (int p = 0; p < 3; p++) {
        int ka = (p == 1) ? 256 : 0;
        int kb = (p == 2) ? 256 : 0;
        #pragma unroll
        for (int ks = 0; ks < 8; ks++) {
            int ofA = ka + ks * 32;
            int ofB = kb + ks * 32;
            uint32_t a[2][4], b[4][2];
            #pragma unroll
            for (int i = 0; i < 2; i++)
                asm volatile("ldmatrix.sync.aligned.m8n8.x4.shared.b16 {%0,%1,%2,%3}, [%4];"
                             : "=r"(a[i][0]), "=r"(a[i][1]), "=r"(a[i][2]), "=r"(a[i][3])
                             : "r"(a_base[i] + ofA));
            #pragma unroll
            for (int j = 0; j < 4; j++)
                asm volatile("ldmatrix.sync.aligned.m8n8.x2.shared.b16 {%0,%1}, [%2];"
                             : "=r"(b[j][0]), "=r"(b[j][1])
                             : "r"(b_base[j] + ofB));
            #pragma unroll
            for (int i = 0; i < 2; i++)
                #pragma unroll
                for (int j = 0; j < 4; j++)
                    asm volatile(
                        "mma.sync.aligned.m16n8k16.row.col.f32.bf16.bf16.f32 "
                        "{%0,%1,%2,%3}, {%4,%5,%6,%7}, {%8,%9}, {%0,%1,%2,%3};"
                        : "+f"(acc[i][j][0]), "+f"(acc[i][j][1]),
                          "+f"(acc[i][j][2]), "+f"(acc[i][j][3])
                        : "r"(a[i][0]), "r"(a[i][1]), "r"(a[i][2]), "r"(a[i][3]),
                          "r"(b[j][0]), "r"(b[j][1]));
        }
    }

    // bias (cols fixed per thread)
    float bias0[4], bias1[4];
    #pragma unroll
    for (int j = 0; j < 4; j++) {
        int c = n0 + wn + j * 8 + (lane & 3) * 2;
        bias0[j] = (c < Vv) ? lmb[c] : 0.f;
        bias1[j] = (c + 1 < Vv) ? lmb[c + 1] : 0.f;
    }

    // epilogue: add bias, store logits (full 32B sectors per 4-lane group), sum exp
    #pragma unroll
    for (int i = 0; i < 2; i++) {
        #pragma unroll
        for (int hf = 0; hf < 2; hf++) {
            int row = m0 + wm + i * 16 + (lane >> 2) + hf * 8;
            size_t ro = (size_t)row * Vv;
            float rexp = 0.f;
            #pragma unroll
            for (int j = 0; j < 4; j++) {
                int c = n0 + wn + j * 8 + (lane & 3) * 2;
                float v0 = acc[i][j][hf * 2]     + bias0[j];
                float v1 = acc[i][j][hf * 2 + 1] + bias1[j];
                if (c < Vv) {
                    if (out) out[ro + c] = v0;
                    rexp += __expf(v0);
                }
                if (c + 1 < Vv) {
                    if (out) out[ro + c + 1] = v1;
                    rexp += __expf(v1);
                }
            }
            rexp += __shfl_xor_sync(0xffffffffu, rexp, 1);
            rexp += __shfl_xor_sync(0xffffffffu, rexp, 2);
            if ((lane & 3) == 0) atomicAdd(&g_rowsum[row], rexp);
        }
    }
}

// ======================= loss =======================
__global__ void rownll_kernel(const int* __restrict__ targets,
                              const float* __restrict__ lm_w,
                              const float* __restrict__ lmb) {
    int gw = (blockIdx.x * blockDim.x + threadIdx.x) >> 5;
    int lane = threadIdx.x & 31;
    for (int r = gw; r < BT; r += 512) {
        int tgt = targets[r];
        float dot = 0.f;
        const float* xr = &g_h[(size_t)r * Dd];
        #pragma unroll
        for (int i = 0; i < 4; i++) {
            int d = lane + 32 * i;
            dot += xr[d] * lm_w[(size_t)d * Vv + tgt];
        }
        #pragma unroll
        for (int o = 16; o; o >>= 1) dot += __shfl_xor_sync(0xffffffffu, dot, o);
        if (lane == 0) g_att[r] = logf(g_rowsum[r]) - (dot + lmb[tgt]);
    }
}

__global__ void lossred_kernel(float* __restrict__ loss_out) {
    int tid = threadIdx.x;
    float local = 0.f;
    for (int r = tid; r < BT; r += 1024) local += g_att[r];
    #pragma unroll
    for (int o = 16; o; o >>= 1) local += __shfl_xor_sync(0xffffffffu, local, o);
    __shared__ float red[32];
    if ((tid & 31) == 0) red[tid >> 5] = local;
    __syncthreads();
    if (tid < 32) {
        float v = red[tid];
        #pragma unroll
        for (int o = 16; o; o >>= 1) v += __shfl_xor_sync(0xffffffffu, v, o);
        if (tid == 0 && loss_out) *loss_out = v * (1.f / (float)BT);
    }
}

// ======================= launch =======================
extern "C" void kernel_launch(void* const* d_in, const int* in_sizes, int n_in,
                              void* d_out, int out_size) {
    const int*   idx     = (const int*)  d_in[0];
    const int*   targets = (const int*)  d_in[1];
    const float* tok_emb = (const float*)d_in[2];
    const float* pos_emb = (const float*)d_in[3];
    const float* wq      = (const float*)d_in[4];
    const float* wk      = (const float*)d_in[5];
    const float* wv      = (const float*)d_in[6];
    const float* wproj   = (const float*)d_in[7];
    const float* bproj   = (const float*)d_in[8];
    const float* w1      = (const float*)d_in[9];
    const float* b1      = (const float*)d_in[10];
    const float* w2      = (const float*)d_in[11];
    const float* b2      = (const float*)d_in[12];
    const float* ln1_g   = (const float*)d_in[13];
    const float* ln1_b   = (const float*)d_in[14];
    const float* ln2_g   = (const float*)d_in[15];
    const float* ln2_b   = (const float*)d_in[16];
    const float* lnf_g   = (const float*)d_in[17];
    const float* lnf_b   = (const float*)d_in[18];
    const float* lm_w    = (const float*)d_in[19];
    const float* lm_b    = (const float*)d_in[20];

    float* outf = (float*)d_out;
    long long btv = (long long)BT * Vv;
    float* logits = ((long long)out_size >= btv) ? outf : nullptr;
    float* lossp  = nullptr;
    if ((long long)out_size == btv + 1) lossp = outf + btv;
    else if ((long long)out_size < btv && out_size >= 1) lossp = outf + (out_size - 1);

    constexpr int LM_SMEM = (128 * LMS + 64 * LMS) * 2;  // 101376
    cudaFuncSetAttribute(lmhead_hmma, cudaFuncAttributeMaxDynamicSharedMemorySize, LM_SMEM);

    prep_kernel<<<256, 256>>>(wq, wk, wv);
    convw_kernel<<<dim3(VP / 32, 4), dim3(32, 8)>>>(lm_w);
    embed_kernel<<<BT, 128>>>(idx, tok_emb, pos_emb);

    for (int l = 0; l < Ll; l++) {
        ln_kernel<<<BT, 128>>>(ln1_g + l * Dd, ln1_b + l * Dd);
        gemm64_kernel<<<dim3(384 / 64, BT / 64), 256>>>(
            1, nullptr, l * Dd * 384, nullptr, 0, 2, 384, 128, 0);
        attn_kernel<<<Bb * Hh, 128>>>();
        gemm64_kernel<<<dim3(128 / 64, BT / 64), 256>>>(
            3, wproj + (size_t)l * Dd * Dd, 0, bproj + l * Dd, 1, 0, 128, 128, 0);
        ln_kernel<<<BT, 128>>>(ln2_g + l * Dd, ln2_b + l * Dd);
        gemm64_kernel<<<dim3(512 / 64, BT / 64), 256>>>(
            1, w1 + (size_t)l * Dd * 4 * Dd, 0, b1 + l * 4 * Dd, 0, 4, 512, 128, 1);
        gemm64_kernel<<<dim3(128 / 64, BT / 64), 256>>>(
            4, w2 + (size_t)l * 4 * Dd * Dd, 0, b2 + l * Dd, 1, 0, 128, 512, 0);
    }
    ln_kernel<<<BT, 128>>>(lnf_g, lnf_b);
    convh_kernel<<<(BT * Dd + 255) / 256, 256>>>();
    lmhead_hmma<<<dim3(BT / 128, VP / 64), 256, LM_SMEM>>>(lm_b, logits);
    rownll_kernel<<<64, 256>>>(targets, lm_w, lm_b);
    lossred_kernel<<<1, 1024>>>(lossp);
}